// round 9
// baseline (speedup 1.0000x reference)
#include <cuda_runtime.h>
#include <cuda_bf16.h>

#define CLS   1000
#define CLS4  250              // CLS / 4
#define CLS2  500              // CLS / 2 (bf16 pairs)
#define NB    65536            // batch
#define TINV  (1.0f/0.3f)
#define SPB   16               // samples per block = warps per block
#define THREADS (SPB * 32)     // 512
#define MAIN_BLOCKS (NB / SPB) // 4096
#define TILE_BYTES (SPB * CLS * 4)  // 64000, multiple of 16

__device__ __nv_bfloat162 g_soft[CLS * CLS2]; // softmax(-S[c]/T) rows, bf16, 2 MB
__device__ float g_partial[MAIN_BLOCKS];      // per-block loss partials
__device__ int   g_t64;                       // 1 if targets are int64
__device__ unsigned int g_count = 0;          // last-block-done counter (self-resetting)

// bf16 -> f32 is exact: high half of the f32 bit pattern.
__device__ __forceinline__ float bflo(unsigned int r) { return __uint_as_float(r << 16); }
__device__ __forceinline__ float bfhi(unsigned int r) { return __uint_as_float(r & 0xFFFF0000u); }

// ---------------------------------------------------------------------------
// SOFT[c][:] = softmax(-S[c][:] / T), bf16. Single-phase (args in [-3.33,0],
// no max needed). One float4 per thread, block-reduce, one bf16x4 store.
// Block 0 / thread 0 sniffs targets dtype (values < 1000 => int64 has all odd
// 32-bit words zero; false-positive prob with int32 data is (1/1000)^32).
// ---------------------------------------------------------------------------
__global__ __launch_bounds__(256) void soft_kernel(const float* __restrict__ S,
                                                   const int* __restrict__ tprobe)
{
    __shared__ float red[8];
    __shared__ float s_inv;
    const int c   = blockIdx.x;
    const int tid = threadIdx.x;

    if (c == 0 && tid == 0) {
        int is64 = 1;
        #pragma unroll
        for (int i = 0; i < 32; i++)
            if (tprobe[2 * i + 1] != 0) { is64 = 0; break; }
        g_t64 = is64;
    }

    const float4* __restrict__ src = (const float4*)(S + (size_t)c * CLS);
    const bool active = tid < CLS4;

    float e0 = 0.f, e1 = 0.f, e2 = 0.f, e3 = 0.f;
    if (active) {
        float4 x = src[tid];
        e0 = __expf(-x.x * TINV);
        e1 = __expf(-x.y * TINV);
        e2 = __expf(-x.z * TINV);
        e3 = __expf(-x.w * TINV);
    }
    float s = (e0 + e1) + (e2 + e3);
    #pragma unroll
    for (int o = 16; o; o >>= 1) s += __shfl_xor_sync(~0u, s, o);
    if ((tid & 31) == 0) red[tid >> 5] = s;
    __syncthreads();
    if (tid == 0) {
        float tot = 0.f;
        #pragma unroll
        for (int i = 0; i < 8; i++) tot += red[i];
        s_inv = 1.0f / tot;
    }
    __syncthreads();

    if (active) {
        const float inv = s_inv;
        uint2 o;
        __nv_bfloat162 lo = __floats2bfloat162_rn(e0 * inv, e1 * inv);
        __nv_bfloat162 hi = __floats2bfloat162_rn(e2 * inv, e3 * inv);
        o.x = *(const unsigned int*)&lo;
        o.y = *(const unsigned int*)&hi;
        ((uint2*)g_soft)[(size_t)c * CLS4 + tid] = o;
    }
}

// ---------------------------------------------------------------------------
// Main pass (bulk-async version): each CTA fetches 16 sample rows (64000 B)
// with ONE cp.async.bulk into smem — the bulk engine streams large contiguous
// requests, bypassing the per-warp LDG path that plateaued at ~5 TB/s.
// While the copy flies, each warp prefetches its bf16 soft row from L2.
// After the mbarrier acquire-wait, warp w computes its sample from smem
// (lane-strided LDS.128, conflict-free). loss_b = log(sum exp x) - dot.
// Final mean folded in via last-block-done (deterministic fixed-order sum).
// ---------------------------------------------------------------------------
__global__ __launch_bounds__(THREADS, 1) void main_kernel(
    const float* __restrict__ logits,
    const void*  __restrict__ targets,
    float* __restrict__ out)
{
    extern __shared__ float tile[];              // SPB * CLS floats = 64000 B
    __shared__ float part[SPB];
    __shared__ bool  isLast;
    __shared__ __align__(8) unsigned long long mbar;

    const int tid  = threadIdx.x;
    const int wid  = tid >> 5;
    const int lane = tid & 31;
    const int gw   = blockIdx.x * SPB + wid;     // sample id for this warp

    const unsigned mb  = (unsigned)__cvta_generic_to_shared(&mbar);
    const unsigned dst = (unsigned)__cvta_generic_to_shared(tile);

    if (tid == 0)
        asm volatile("mbarrier.init.shared::cta.b64 [%0], 1;" :: "r"(mb) : "memory");
    __syncthreads();

    if (tid == 0) {
        asm volatile("mbarrier.arrive.expect_tx.shared::cta.b64 _, [%0], %1;"
                     :: "r"(mb), "r"((unsigned)TILE_BYTES) : "memory");
        const float* src = logits + (size_t)blockIdx.x * (SPB * CLS);
        asm volatile("cp.async.bulk.shared::cluster.global.mbarrier::complete_tx::bytes "
                     "[%0], [%1], %2, [%3];"
                     :: "r"(dst), "l"(src), "r"((unsigned)TILE_BYTES), "r"(mb) : "memory");
    }

    // ---- overlap with the bulk copy: target + soft-row gather from L2 ----
    long long t;
    if (g_t64) t = ((const long long*)targets)[gw];
    else       t = ((const int*)targets)[gw];

    const uint2* __restrict__ sf = (const uint2*)g_soft + (size_t)t * CLS4;
    uint2 sr[8];
    #pragma unroll
    for (int i = 0; i < 7; i++) sr[i] = __ldg(&sf[lane + 32 * i]);
    if (lane < 26) sr[7] = __ldg(&sf[lane + 224]);
    else           sr[7] = make_uint2(0u, 0u);

    // ---- wait for the tile (acquire orders the async writes for our LDS) ----
    {
        unsigned done;
        do {
            asm volatile("{\n\t.reg .pred p;\n\t"
                         "mbarrier.try_wait.parity.acquire.cta.shared::cta.b64 p, [%1], %2;\n\t"
                         "selp.b32 %0, 1, 0, p;\n\t}"
                         : "=r"(done) : "r"(mb), "r"(0u) : "memory");
        } while (!done);
    }

    // ---- compute from smem: fused exp + dot, dual accumulators ----
    const float4* __restrict__ row = (const float4*)(tile + wid * CLS);
    float s0 = 0.f, s1 = 0.f, d0 = 0.f, d1 = 0.f;
    #pragma unroll
    for (int i = 0; i < 7; i++) {
        float4 x = row[lane + 32 * i];
        d0 += x.x * bflo(sr[i].x) + x.z * bflo(sr[i].y);
        d1 += x.y * bfhi(sr[i].x) + x.w * bfhi(sr[i].y);
        s0 += __expf(x.x) + __expf(x.z);
        s1 += __expf(x.y) + __expf(x.w);
    }
    if (lane < 26) {
        float4 x = row[lane + 224];
        d0 += x.x * bflo(sr[7].x) + x.z * bflo(sr[7].y);
        d1 += x.y * bfhi(sr[7].x) + x.w * bfhi(sr[7].y);
        s0 += __expf(x.x) + __expf(x.z);
        s1 += __expf(x.y) + __expf(x.w);
    }
    float s = s0 + s1, dot = d0 + d1;

    #pragma unroll
    for (int o = 16; o; o >>= 1) {
        s   += __shfl_xor_sync(~0u, s,   o);
        dot += __shfl_xor_sync(~0u, dot, o);
    }

    if (lane == 0)
        part[wid] = __logf(s) - dot;
    __syncthreads();

    if (tid == 0) {
        float acc = 0.f;
        #pragma unroll
        for (int i = 0; i < SPB; i++) acc += part[i];
        g_partial[blockIdx.x] = acc;
        __threadfence();
        unsigned int done = atomicAdd(&g_count, 1u);
        isLast = (done == (unsigned int)(MAIN_BLOCKS - 1));
    }
    __syncthreads();

    if (isLast) {
        // 512 threads fold 4096 partials (1024 float4), fixed order: deterministic.
        float acc = 0.f;
        for (int i = tid; i < MAIN_BLOCKS / 4; i += THREADS) {
            float4 v = ((const float4*)g_partial)[i];
            acc += (v.x + v.y) + (v.z + v.w);
        }
        #pragma unroll
        for (int o = 16; o; o >>= 1) acc += __shfl_xor_sync(~0u, acc, o);
        if (lane == 0) part[wid] = acc;
        __syncthreads();
        if (tid == 0) {
            float tot = 0.f;
            #pragma unroll
            for (int i = 0; i < SPB; i++) tot += part[i];
            out[0] = tot * (1.0f / (float)NB);
            g_count = 0;                      // self-reset for next graph replay
        }
    }
}

extern "C" void kernel_launch(void* const* d_in, const int* in_sizes, int n_in,
                              void* d_out, int out_size)
{
    const float* logits  = (const float*)d_in[0];
    const void*  targets = d_in[1];
    const float* simmat  = (const float*)d_in[2];
    float* out = (float*)d_out;

    // Opt in to >48 KB dynamic smem (attribute set, not an allocation).
    cudaFuncSetAttribute(main_kernel, cudaFuncAttributeMaxDynamicSharedMemorySize,
                         TILE_BYTES);

    soft_kernel<<<CLS, 256>>>(simmat, (const int*)targets);
    main_kernel<<<MAIN_BLOCKS, THREADS, TILE_BYTES>>>(logits, targets, out);
}

// round 10
// speedup vs baseline: 1.2167x; 1.2167x over previous
#include <cuda_runtime.h>
#include <cuda_bf16.h>

#define CLS    1000
#define CLS4   250               // CLS / 4
#define CLS2   500               // CLS / 2 (bf16 pairs)
#define NB     65536             // batch
#define TINV   (1.0f/0.3f)
#define TPS    16                // samples per tile (= consumer warps)
#define NTILES (NB / TPS)        // 4096
#define GRID   148               // persistent: 1 CTA per SM
#define CWARPS 16                // consumer warps
#define THREADS ((CWARPS + 1) * 32)   // 544: +1 producer warp
#define STAGES 2
#define STAGE_BYTES (TPS * CLS * 4)   // 64000, multiple of 16
#define SMEM_DYN (STAGES * STAGE_BYTES)

__device__ __nv_bfloat162 g_soft[CLS * CLS2]; // softmax(-S[c]/T) rows, bf16, 2 MB
__device__ float g_partial[GRID];             // per-CTA loss partials
__device__ int   g_t64;                       // 1 if targets are int64
__device__ unsigned int g_count = 0;          // last-block-done counter (self-resetting)

__device__ __forceinline__ float bflo(unsigned int r) { return __uint_as_float(r << 16); }
__device__ __forceinline__ float bfhi(unsigned int r) { return __uint_as_float(r & 0xFFFF0000u); }

__device__ __forceinline__ void mbar_wait(unsigned mb, unsigned parity)
{
    unsigned done;
    do {
        asm volatile("{\n\t.reg .pred p;\n\t"
                     "mbarrier.try_wait.parity.acquire.cta.shared::cta.b64 p, [%1], %2, 0x989680;\n\t"
                     "selp.b32 %0, 1, 0, p;\n\t}"
                     : "=r"(done) : "r"(mb), "r"(parity) : "memory");
    } while (!done);
}

// ---------------------------------------------------------------------------
// SOFT[c][:] = softmax(-S[c][:] / T), bf16. Single-phase (args in [-3.33,0]).
// Block 0 / thread 0 sniffs targets dtype (values < 1000 => int64 has all odd
// 32-bit words zero; false-positive prob with int32 data is (1/1000)^32).
// ---------------------------------------------------------------------------
__global__ __launch_bounds__(256) void soft_kernel(const float* __restrict__ S,
                                                   const int* __restrict__ tprobe)
{
    __shared__ float red[8];
    __shared__ float s_inv;
    const int c   = blockIdx.x;
    const int tid = threadIdx.x;

    if (c == 0 && tid == 0) {
        int is64 = 1;
        #pragma unroll
        for (int i = 0; i < 32; i++)
            if (tprobe[2 * i + 1] != 0) { is64 = 0; break; }
        g_t64 = is64;
    }

    const float4* __restrict__ src = (const float4*)(S + (size_t)c * CLS);
    const bool active = tid < CLS4;

    float e0 = 0.f, e1 = 0.f, e2 = 0.f, e3 = 0.f;
    if (active) {
        float4 x = src[tid];
        e0 = __expf(-x.x * TINV);
        e1 = __expf(-x.y * TINV);
        e2 = __expf(-x.z * TINV);
        e3 = __expf(-x.w * TINV);
    }
    float s = (e0 + e1) + (e2 + e3);
    #pragma unroll
    for (int o = 16; o; o >>= 1) s += __shfl_xor_sync(~0u, s, o);
    if ((tid & 31) == 0) red[tid >> 5] = s;
    __syncthreads();
    if (tid == 0) {
        float tot = 0.f;
        #pragma unroll
        for (int i = 0; i < 8; i++) tot += red[i];
        s_inv = 1.0f / tot;
    }
    __syncthreads();

    if (active) {
        const float inv = s_inv;
        uint2 o;
        __nv_bfloat162 lo = __floats2bfloat162_rn(e0 * inv, e1 * inv);
        __nv_bfloat162 hi = __floats2bfloat162_rn(e2 * inv, e3 * inv);
        o.x = *(const unsigned int*)&lo;
        o.y = *(const unsigned int*)&hi;
        ((uint2*)g_soft)[(size_t)c * CLS4 + tid] = o;
    }
}

// ---------------------------------------------------------------------------
// Persistent warp-specialized pipeline. 148 CTAs (1/SM), 17 warps.
// Warp 16 (producer, lane 0): double-buffered cp.async.bulk of 64 KB tiles —
// a copy is ALWAYS in flight, so DRAM never idles on compute phases (R9's
// single-buffer bug). Warps 0-15 (consumers): sample w of each tile; prefetch
// bf16 soft row from L2 during the copy, then fused exp+dot from smem.
// Stage cursors: tile k -> stage k&1, full parity (k>>1)&1, producer empty
// parity ((k>>1)+1)&1 (first two waits pass immediately on fresh barriers).
// ---------------------------------------------------------------------------
__global__ __launch_bounds__(THREADS, 1) void main_kernel(
    const float* __restrict__ logits,
    const void*  __restrict__ targets,
    float* __restrict__ out)
{
    extern __shared__ float tile[];               // STAGES * TPS * CLS floats
    __shared__ __align__(8) unsigned long long full_bar[STAGES], empty_bar[STAGES];
    __shared__ float part[CWARPS + 1];
    __shared__ bool  isLast;

    const int tid  = threadIdx.x;
    const int wid  = tid >> 5;
    const int lane = tid & 31;
    const int bid  = blockIdx.x;

    const unsigned full0  = (unsigned)__cvta_generic_to_shared(&full_bar[0]);
    const unsigned empty0 = (unsigned)__cvta_generic_to_shared(&empty_bar[0]);
    const unsigned dst0   = (unsigned)__cvta_generic_to_shared(tile);

    if (tid == 0) {
        #pragma unroll
        for (int s = 0; s < STAGES; s++) {
            asm volatile("mbarrier.init.shared::cta.b64 [%0], 1;"  :: "r"(full0  + 8u*s) : "memory");
            asm volatile("mbarrier.init.shared::cta.b64 [%0], %1;" :: "r"(empty0 + 8u*s), "r"(CWARPS) : "memory");
        }
    }
    __syncthreads();

    const int t64 = g_t64;

    if (wid == CWARPS) {
        // ---------------- producer ----------------
        if (lane == 0) {
            int k = 0;
            for (int t = bid; t < NTILES; t += GRID, k++) {
                const int s = k & 1;
                mbar_wait(empty0 + 8u*s, ((unsigned)(k >> 1) + 1u) & 1u);
                asm volatile("mbarrier.arrive.expect_tx.shared::cta.b64 _, [%0], %1;"
                             :: "r"(full0 + 8u*s), "r"((unsigned)STAGE_BYTES) : "memory");
                const float* src = logits + (size_t)t * (TPS * CLS);
                asm volatile("cp.async.bulk.shared::cluster.global.mbarrier::complete_tx::bytes "
                             "[%0], [%1], %2, [%3];"
                             :: "r"(dst0 + (unsigned)(s * STAGE_BYTES)), "l"(src),
                                "r"((unsigned)STAGE_BYTES), "r"(full0 + 8u*s) : "memory");
            }
        }
        if (lane == 0) part[CWARPS] = 0.f;
    } else {
        // ---------------- consumers ----------------
        float loss = 0.f;
        int k = 0;
        for (int t = bid; t < NTILES; t += GRID, k++) {
            const int s = k & 1;
            const int gw = t * TPS + wid;          // sample id

            // prefetch target + soft row from L2 (overlaps the bulk copy)
            long long tg;
            if (t64) tg = ((const long long*)targets)[gw];
            else     tg = ((const int*)targets)[gw];
            const uint2* __restrict__ sf = (const uint2*)g_soft + (size_t)tg * CLS4;
            uint2 sr[8];
            #pragma unroll
            for (int i = 0; i < 7; i++) sr[i] = __ldg(&sf[lane + 32 * i]);
            if (lane < 26) sr[7] = __ldg(&sf[lane + 224]);
            else           sr[7] = make_uint2(0u, 0u);

            mbar_wait(full0 + 8u*s, (unsigned)(k >> 1) & 1u);

            const float4* __restrict__ row =
                (const float4*)(tile + s * (TPS * CLS) + wid * CLS);
            float s0 = 0.f, s1 = 0.f, d0 = 0.f, d1 = 0.f;
            #pragma unroll
            for (int i = 0; i < 7; i++) {
                float4 x = row[lane + 32 * i];
                d0 += x.x * bflo(sr[i].x) + x.z * bflo(sr[i].y);
                d1 += x.y * bfhi(sr[i].x) + x.w * bfhi(sr[i].y);
                s0 += __expf(x.x) + __expf(x.z);
                s1 += __expf(x.y) + __expf(x.w);
            }
            if (lane < 26) {
                float4 x = row[lane + 224];
                d0 += x.x * bflo(sr[7].x) + x.z * bflo(sr[7].y);
                d1 += x.y * bfhi(sr[7].x) + x.w * bfhi(sr[7].y);
                s0 += __expf(x.x) + __expf(x.z);
                s1 += __expf(x.y) + __expf(x.w);
            }
            float es = s0 + s1, dot = d0 + d1;
            #pragma unroll
            for (int o = 16; o; o >>= 1) {
                es  += __shfl_xor_sync(~0u, es,  o);
                dot += __shfl_xor_sync(~0u, dot, o);
            }
            if (lane == 0) loss += __logf(es) - dot;

            __syncwarp();
            if (lane == 0)
                asm volatile("mbarrier.arrive.shared::cta.b64 _, [%0];"
                             :: "r"(empty0 + 8u*s) : "memory");
        }
        if (lane == 0) part[wid] = loss;
    }

    __syncthreads();

    if (tid == 0) {
        float acc = 0.f;
        #pragma unroll
        for (int i = 0; i < CWARPS; i++) acc += part[i];
        g_partial[bid] = acc;
        __threadfence();
        unsigned int done = atomicAdd(&g_count, 1u);
        isLast = (done == (unsigned int)(GRID - 1));
    }
    __syncthreads();

    if (isLast && wid == 0) {
        // 32 lanes fold 148 partials, fixed order: deterministic.
        float acc = 0.f;
        for (int i = lane; i < GRID; i += 32) acc += g_partial[i];
        #pragma unroll
        for (int o = 16; o; o >>= 1) acc += __shfl_xor_sync(~0u, acc, o);
        if (lane == 0) {
            out[0] = acc * (1.0f / (float)NB);
            g_count = 0;                      // self-reset for next graph replay
        }
    }
}

extern "C" void kernel_launch(void* const* d_in, const int* in_sizes, int n_in,
                              void* d_out, int out_size)
{
    const float* logits  = (const float*)d_in[0];
    const void*  targets = d_in[1];
    const float* simmat  = (const float*)d_in[2];
    float* out = (float*)d_out;

    cudaFuncSetAttribute(main_kernel, cudaFuncAttributeMaxDynamicSharedMemorySize,
                         SMEM_DYN);

    soft_kernel<<<CLS, 256>>>(simmat, (const int*)targets);
    main_kernel<<<GRID, THREADS, SMEM_DYN>>>(logits, targets, out);
}